// round 11
// baseline (speedup 1.0000x reference)
#include <cuda_runtime.h>
#include <cuda_bf16.h>
#include <math.h>

// Problem constants (match reference)
#define N_NODES 50000
#define E_EDGES 800000
#define K_IN    256
#define M_OUT   128   // H*D = 4*32
#define H_HEADS 4
#define D_HEAD  32
#define NEG_SLOPE 0.2f

// ---------------- scratch (device globals; no allocation allowed) ----------
__device__ float g_ft[(size_t)N_NODES * M_OUT];   // projected features [N,128]
__device__ float g_el[N_NODES * H_HEADS];         // per-node left logits
__device__ float g_er[N_NODES * H_HEADS];         // per-node right logits
__device__ int   g_deg[N_NODES];
__device__ int   g_cur[N_NODES];
__device__ int   g_off[N_NODES + 1];
__device__ int   g_csr_src[E_EDGES];

// ---------------- f32x2 packed-FMA helpers (sm_100+) ----------------------
__device__ __forceinline__ unsigned long long pack2(float x, float y) {
    unsigned long long r;
    asm("mov.b64 %0, {%1,%2};" : "=l"(r) : "f"(x), "f"(y));
    return r;
}
__device__ __forceinline__ void unpack2(unsigned long long v, float& x, float& y) {
    asm("mov.b64 {%0,%1}, %2;" : "=f"(x), "=f"(y) : "l"(v));
}
__device__ __forceinline__ void ffma2(unsigned long long& d, unsigned long long a,
                                      unsigned long long b) {
    asm("fma.rn.f32x2 %0, %1, %2, %0;" : "+l"(d) : "l"(a), "l"(b));
}

// ---------------- kernel 0: zero counters ---------------------------------
__global__ void zero_kernel() {
    int i = blockIdx.x * blockDim.x + threadIdx.x;
    if (i < N_NODES) { g_deg[i] = 0; g_cur[i] = 0; }
}

// ---------------- kernel 1: GEMM ft = feat @ W  (fp32, f32x2 FMA) ---------
// Block tile: 32 rows x 128 cols. 256 threads: ty=tid/32 owns 4 rows,
// tx=tid%32 owns 4 cols. K tiled by 32.
#define BR 32
#define KC 32
#define AS_LD 36    // pad to avoid store bank conflicts, keeps 16B alignment
#define BS_LD 132

__global__ __launch_bounds__(256) void gemm_kernel(const float* __restrict__ A,
                                                   const float* __restrict__ B) {
    __shared__ float As[BR][AS_LD];
    __shared__ float Bs[KC][BS_LD];

    const int tid  = threadIdx.x;
    const int row0 = blockIdx.x * BR;
    const int ty   = tid >> 5;   // 0..7
    const int tx   = tid & 31;   // 0..31

    unsigned long long acc[4][2];
#pragma unroll
    for (int i = 0; i < 4; i++) { acc[i][0] = 0ULL; acc[i][1] = 0ULL; }

    for (int k0 = 0; k0 < K_IN; k0 += KC) {
        // load A tile: 32 rows x 32 k
        {
            int r  = tid >> 3;        // 0..31
            int kk = (tid & 7) * 4;   // 0..28
            int gr = row0 + r;
            float4 v = make_float4(0.f, 0.f, 0.f, 0.f);
            if (gr < N_NODES)
                v = *reinterpret_cast<const float4*>(&A[(size_t)gr * K_IN + k0 + kk]);
            *reinterpret_cast<float4*>(&As[r][kk]) = v;
        }
        // load B tile: 32 k x 128 cols
        {
            int kr    = tid >> 3;          // 0..31
            int cbase = (tid & 7) * 16;    // 0..112
            const float* srcp = &B[(size_t)(k0 + kr) * M_OUT + cbase];
#pragma unroll
            for (int q = 0; q < 4; q++) {
                float4 v = *reinterpret_cast<const float4*>(srcp + q * 4);
                *reinterpret_cast<float4*>(&Bs[kr][cbase + q * 4]) = v;
            }
        }
        __syncthreads();

#pragma unroll
        for (int kk = 0; kk < KC; kk += 4) {
            float4 av[4];
#pragma unroll
            for (int i = 0; i < 4; i++)
                av[i] = *reinterpret_cast<const float4*>(&As[ty * 4 + i][kk]);
#pragma unroll
            for (int q = 0; q < 4; q++) {
                float4 b = *reinterpret_cast<const float4*>(&Bs[kk + q][tx * 4]);
                unsigned long long b01 = pack2(b.x, b.y);
                unsigned long long b23 = pack2(b.z, b.w);
#pragma unroll
                for (int i = 0; i < 4; i++) {
                    float a = (q == 0) ? av[i].x : (q == 1) ? av[i].y
                              : (q == 2) ? av[i].z : av[i].w;
                    unsigned long long aa = pack2(a, a);
                    ffma2(acc[i][0], aa, b01);
                    ffma2(acc[i][1], aa, b23);
                }
            }
        }
        __syncthreads();
    }

#pragma unroll
    for (int i = 0; i < 4; i++) {
        int gr = row0 + ty * 4 + i;
        if (gr < N_NODES) {
            float4 o;
            unpack2(acc[i][0], o.x, o.y);
            unpack2(acc[i][1], o.z, o.w);
            *reinterpret_cast<float4*>(&g_ft[(size_t)gr * M_OUT + tx * 4]) = o;
        }
    }
}

// ---------------- kernel 2: per-node attention logits ---------------------
// one warp per node; lane owns 4 of 128 cols; reduce within 8-lane head group
__global__ __launch_bounds__(256) void eler_kernel(const float* __restrict__ attn_l,
                                                   const float* __restrict__ attn_r) {
    int gw   = (blockIdx.x * blockDim.x + threadIdx.x) >> 5;
    int lane = threadIdx.x & 31;
    if (gw >= N_NODES) return;

    float4 f  = *reinterpret_cast<const float4*>(&g_ft[(size_t)gw * M_OUT + lane * 4]);
    float4 al = *reinterpret_cast<const float4*>(&attn_l[lane * 4]);
    float4 ar = *reinterpret_cast<const float4*>(&attn_r[lane * 4]);
    float pl = f.x * al.x + f.y * al.y + f.z * al.z + f.w * al.w;
    float pr = f.x * ar.x + f.y * ar.y + f.z * ar.z + f.w * ar.w;
#pragma unroll
    for (int o = 1; o < 8; o <<= 1) {
        pl += __shfl_xor_sync(0xFFFFFFFFu, pl, o);
        pr += __shfl_xor_sync(0xFFFFFFFFu, pr, o);
    }
    if ((lane & 7) == 0) {
        g_el[gw * H_HEADS + (lane >> 3)] = pl;
        g_er[gw * H_HEADS + (lane >> 3)] = pr;
    }
}

// ---------------- kernel 3: in-degree histogram ----------------------------
__global__ void hist_kernel(const int* __restrict__ dst) {
    int e = blockIdx.x * blockDim.x + threadIdx.x;
    if (e < E_EDGES) atomicAdd(&g_deg[dst[e]], 1);
}

// ---------------- kernel 4: exclusive scan (single block) ------------------
__global__ __launch_bounds__(1024) void scan_kernel() {
    __shared__ int warp_sums[32];
    __shared__ int s_base;
    const int tid  = threadIdx.x;
    const int lane = tid & 31;
    const int w    = tid >> 5;
    if (tid == 0) { s_base = 0; g_off[0] = 0; }
    __syncthreads();

    for (int base = 0; base < N_NODES; base += 1024) {
        int i = base + tid;
        int v = (i < N_NODES) ? g_deg[i] : 0;
        int x = v;
#pragma unroll
        for (int o = 1; o < 32; o <<= 1) {
            int y = __shfl_up_sync(0xFFFFFFFFu, x, o);
            if (lane >= o) x += y;
        }
        if (lane == 31) warp_sums[w] = x;
        __syncthreads();
        if (w == 0) {
            int y = warp_sums[lane];
#pragma unroll
            for (int o = 1; o < 32; o <<= 1) {
                int z = __shfl_up_sync(0xFFFFFFFFu, y, o);
                if (lane >= o) y += z;
            }
            warp_sums[lane] = y;
        }
        __syncthreads();
        int incl = x + (w > 0 ? warp_sums[w - 1] : 0) + s_base;
        if (i < N_NODES) g_off[i + 1] = incl;
        __syncthreads();
        if (tid == 1023) s_base = incl;
        __syncthreads();
    }
}

// ---------------- kernel 5: scatter edges into CSR-by-dst ------------------
__global__ void scatter_kernel(const int* __restrict__ src,
                               const int* __restrict__ dst) {
    int e = blockIdx.x * blockDim.x + threadIdx.x;
    if (e < E_EDGES) {
        int d   = dst[e];
        int pos = g_off[d] + atomicAdd(&g_cur[d], 1);
        g_csr_src[pos] = src[e];
    }
}

// ---------------- kernel 6: softmax + aggregation, 1 warp / dst node -------
__global__ __launch_bounds__(256) void agg_kernel(const float* __restrict__ bias,
                                                  float* __restrict__ out) {
    int d    = (blockIdx.x * blockDim.x + threadIdx.x) >> 5;
    int lane = threadIdx.x & 31;
    if (d >= N_NODES) return;

    int start = g_off[d];
    int end   = g_off[d + 1];

    int h4 = lane & 3;    // head for pass 1 (lane = (edge_phase, head))
    int h  = lane >> 3;   // head owning this lane's 4 output dims in pass 2
    float er1 = g_er[d * H_HEADS + h4];
    float er2 = g_er[d * H_HEADS + h];

    // pass 1: per-head max over incoming edges
    float mx = -INFINITY;
    for (int j = start + (lane >> 2); j < end; j += 8) {
        int s   = g_csr_src[j];
        float x = g_el[s * H_HEADS + h4] + er1;
        x = (x > 0.f) ? x : NEG_SLOPE * x;
        mx = fmaxf(mx, x);
    }
    mx = fmaxf(mx, __shfl_xor_sync(0xFFFFFFFFu, mx, 4));
    mx = fmaxf(mx, __shfl_xor_sync(0xFFFFFFFFu, mx, 8));
    mx = fmaxf(mx, __shfl_xor_sync(0xFFFFFFFFu, mx, 16));
    float m2 = __shfl_sync(0xFFFFFFFFu, mx, h);   // lane h holds head-h max

    // pass 2: weighted accumulate; lane owns dims [lane*4, lane*4+4)
    float4 acc = make_float4(0.f, 0.f, 0.f, 0.f);
    float ssum = 0.f;
    for (int j = start; j < end; ++j) {
        int s   = g_csr_src[j];
        float x = g_el[s * H_HEADS + h] + er2;
        x = (x > 0.f) ? x : NEG_SLOPE * x;
        float a = __expf(x - m2);
        if ((lane & 7) == 0) ssum += a;
        float4 f = *reinterpret_cast<const float4*>(
            &g_ft[(size_t)s * M_OUT + lane * 4]);
        acc.x += f.x * a; acc.y += f.y * a; acc.z += f.z * a; acc.w += f.w * a;
    }
    float stot = __shfl_sync(0xFFFFFFFFu, ssum, h << 3);
    float inv  = (end > start) ? 1.f / stot : 0.f;

    float4 b = *reinterpret_cast<const float4*>(&bias[lane * 4]);
    float4 o;
    o.x = acc.x * inv + b.x;
    o.y = acc.y * inv + b.y;
    o.z = acc.z * inv + b.z;
    o.w = acc.w * inv + b.w;
    *reinterpret_cast<float4*>(&out[(size_t)d * M_OUT + lane * 4]) = o;
}

// ---------------- launch ----------------------------------------------------
extern "C" void kernel_launch(void* const* d_in, const int* in_sizes, int n_in,
                              void* d_out, int out_size) {
    const float* feat   = (const float*)d_in[0];
    const int*   src    = (const int*)d_in[1];
    const int*   dst    = (const int*)d_in[2];
    const float* W      = (const float*)d_in[3];
    const float* attn_l = (const float*)d_in[4];
    const float* attn_r = (const float*)d_in[5];
    const float* bias   = (const float*)d_in[6];
    float* out = (float*)d_out;

    zero_kernel<<<(N_NODES + 255) / 256, 256>>>();
    gemm_kernel<<<(N_NODES + BR - 1) / BR, 256>>>(feat, W);
    eler_kernel<<<(N_NODES + 7) / 8, 256>>>(attn_l, attn_r);
    hist_kernel<<<(E_EDGES + 255) / 256, 256>>>(dst);
    scan_kernel<<<1, 1024>>>();
    scatter_kernel<<<(E_EDGES + 255) / 256, 256>>>(src, dst);
    agg_kernel<<<(N_NODES + 7) / 8, 256>>>(bias, out);
}

// round 12
// speedup vs baseline: 1.0978x; 1.0978x over previous
#include <cuda_runtime.h>
#include <cuda_bf16.h>
#include <math.h>

// Problem constants (match reference)
#define N_NODES 50000
#define E_EDGES 800000
#define K_IN    256
#define M_OUT   128   // H*D = 4*32
#define H_HEADS 4
#define D_HEAD  32
#define NEG_SLOPE 0.2f

typedef unsigned long long ull;

// ---------------- scratch (device globals; no allocation allowed) ----------
__device__ float g_ft[(size_t)N_NODES * M_OUT];   // projected features [N,128]
__device__ float g_el[N_NODES * H_HEADS];         // per-node left logits
__device__ float g_er[N_NODES * H_HEADS];         // per-node right logits
__device__ int   g_deg[N_NODES];
__device__ int   g_pos[N_NODES];                  // running fill cursor (init = offsets)
__device__ int   g_off[N_NODES + 1];
__device__ int   g_csr_src[E_EDGES];

// ---------------- f32x2 packed-FMA helpers (sm_100+) ----------------------
__device__ __forceinline__ ull pack2(float x, float y) {
    ull r;
    asm("mov.b64 %0, {%1,%2};" : "=l"(r) : "f"(x), "f"(y));
    return r;
}
__device__ __forceinline__ void unpack2(ull v, float& x, float& y) {
    asm("mov.b64 {%0,%1}, %2;" : "=f"(x), "=f"(y) : "l"(v));
}
__device__ __forceinline__ void ffma2(ull& d, ull a, ull b) {
    asm("fma.rn.f32x2 %0, %1, %2, %0;" : "+l"(d) : "l"(a), "l"(b));
}

// ---------------- kernel 0: zero degree counters (int4) --------------------
__global__ void zero_kernel() {
    int i = blockIdx.x * blockDim.x + threadIdx.x;   // 12500 int4
    if (i * 4 < N_NODES)
        *reinterpret_cast<int4*>(&g_deg[i * 4]) = make_int4(0, 0, 0, 0);
}

// ---------------- kernel 1: GEMM ft = feat @ W + fused el/er ---------------
// 64 rows x 128 cols per block, 256 threads.
// warp ty owns rows ty*8..ty*8+7; lane tx owns cols tx*4..tx*4+3.
// A tile stored in smem as duplicated (a,a) f32x2 pairs -> broadcast LDS.128.
// B tile read directly as native f32x2 pairs (adjacent cols) -> no packing.
#define BR 64
#define KC 32
#define BS_LD 132

__global__ __launch_bounds__(256) void gemm_kernel(const float* __restrict__ A,
                                                   const float* __restrict__ B,
                                                   const float* __restrict__ attn_l,
                                                   const float* __restrict__ attn_r) {
    __shared__ ull   As2[KC][BR];      // 16 KB, [k][row] duplicated pairs
    __shared__ float Bs[KC][BS_LD];    // ~16.9 KB

    const int tid  = threadIdx.x;
    const int row0 = blockIdx.x * BR;
    const int ty   = tid >> 5;   // 0..7
    const int tx   = tid & 31;   // 0..31

    // attn slices for fused epilogue
    const float4 al = *reinterpret_cast<const float4*>(&attn_l[tx * 4]);
    const float4 ar = *reinterpret_cast<const float4*>(&attn_r[tx * 4]);

    ull acc[8][2];
#pragma unroll
    for (int i = 0; i < 8; i++) { acc[i][0] = 0ULL; acc[i][1] = 0ULL; }

    // A fill: row = tid>>2 (0..63), k offsets (tid&3)*8 .. +7  (8 floats/thread)
    const int a_r = tid >> 2;
    const int a_k = (tid & 3) * 8;
    // B fill: k row = tid>>3 (0..31), col base (tid&7)*16 (16 floats/thread)
    const int b_k = tid >> 3;
    const int b_c = (tid & 7) * 16;

    for (int k0 = 0; k0 < K_IN; k0 += KC) {
        {
            int gr = row0 + a_r;
            float4 v0 = make_float4(0.f, 0.f, 0.f, 0.f), v1 = v0;
            if (gr < N_NODES) {
                const float* ap = &A[(size_t)gr * K_IN + k0 + a_k];
                v0 = *reinterpret_cast<const float4*>(ap);
                v1 = *reinterpret_cast<const float4*>(ap + 4);
            }
            As2[a_k + 0][a_r] = pack2(v0.x, v0.x);
            As2[a_k + 1][a_r] = pack2(v0.y, v0.y);
            As2[a_k + 2][a_r] = pack2(v0.z, v0.z);
            As2[a_k + 3][a_r] = pack2(v0.w, v0.w);
            As2[a_k + 4][a_r] = pack2(v1.x, v1.x);
            As2[a_k + 5][a_r] = pack2(v1.y, v1.y);
            As2[a_k + 6][a_r] = pack2(v1.z, v1.z);
            As2[a_k + 7][a_r] = pack2(v1.w, v1.w);
        }
        {
            const float* bp = &B[(size_t)(k0 + b_k) * M_OUT + b_c];
#pragma unroll
            for (int q = 0; q < 4; q++)
                *reinterpret_cast<float4*>(&Bs[b_k][b_c + q * 4]) =
                    *reinterpret_cast<const float4*>(bp + q * 4);
        }
        __syncthreads();

#pragma unroll
        for (int k = 0; k < KC; k++) {
            // 2 b-pairs (4 cols), no packing needed
            ulonglong2 bb = *reinterpret_cast<const ulonglong2*>(&Bs[k][tx * 4]);
            // 8 a-pairs (8 rows) via 4 broadcast LDS.128
            const ulonglong2* arow =
                reinterpret_cast<const ulonglong2*>(&As2[k][ty * 8]);
            ulonglong2 a01 = arow[0];
            ulonglong2 a23 = arow[1];
            ulonglong2 a45 = arow[2];
            ulonglong2 a67 = arow[3];
            ffma2(acc[0][0], a01.x, bb.x); ffma2(acc[0][1], a01.x, bb.y);
            ffma2(acc[1][0], a01.y, bb.x); ffma2(acc[1][1], a01.y, bb.y);
            ffma2(acc[2][0], a23.x, bb.x); ffma2(acc[2][1], a23.x, bb.y);
            ffma2(acc[3][0], a23.y, bb.x); ffma2(acc[3][1], a23.y, bb.y);
            ffma2(acc[4][0], a45.x, bb.x); ffma2(acc[4][1], a45.x, bb.y);
            ffma2(acc[5][0], a45.y, bb.x); ffma2(acc[5][1], a45.y, bb.y);
            ffma2(acc[6][0], a67.x, bb.x); ffma2(acc[6][1], a67.x, bb.y);
            ffma2(acc[7][0], a67.y, bb.x); ffma2(acc[7][1], a67.y, bb.y);
        }
        __syncthreads();
    }

    // epilogue: store ft rows + fused el/er (dot with attn over 8-lane head groups)
#pragma unroll
    for (int i = 0; i < 8; i++) {
        int gr = row0 + ty * 8 + i;
        if (gr < N_NODES) {
            float4 o;
            unpack2(acc[i][0], o.x, o.y);
            unpack2(acc[i][1], o.z, o.w);
            *reinterpret_cast<float4*>(&g_ft[(size_t)gr * M_OUT + tx * 4]) = o;

            float pl = o.x * al.x + o.y * al.y + o.z * al.z + o.w * al.w;
            float pr = o.x * ar.x + o.y * ar.y + o.z * ar.z + o.w * ar.w;
#pragma unroll
            for (int off = 1; off < 8; off <<= 1) {
                pl += __shfl_xor_sync(0xFFFFFFFFu, pl, off);
                pr += __shfl_xor_sync(0xFFFFFFFFu, pr, off);
            }
            if ((tx & 7) == 0) {
                g_el[gr * H_HEADS + (tx >> 3)] = pl;
                g_er[gr * H_HEADS + (tx >> 3)] = pr;
            }
        }
    }
}

// ---------------- kernel 2: in-degree histogram (4 edges/thread) -----------
__global__ void hist_kernel(const int* __restrict__ dst) {
    int i = blockIdx.x * blockDim.x + threadIdx.x;   // 200000 threads
    if (i * 4 < E_EDGES) {
        int4 d4 = *reinterpret_cast<const int4*>(&dst[i * 4]);
        atomicAdd(&g_deg[d4.x], 1);
        atomicAdd(&g_deg[d4.y], 1);
        atomicAdd(&g_deg[d4.z], 1);
        atomicAdd(&g_deg[d4.w], 1);
    }
}

// ---------------- kernel 3: exclusive scan, 4 elems/thread, 1 block --------
__global__ __launch_bounds__(1024) void scan_kernel() {
    __shared__ int warp_sums[32];
    __shared__ int s_base;
    const int tid  = threadIdx.x;
    const int lane = tid & 31;
    const int w    = tid >> 5;
    if (tid == 0) { s_base = 0; g_off[0] = 0; }
    __syncthreads();

    for (int base = 0; base < N_NODES; base += 4096) {
        int i4 = base + tid * 4;
        int4 v = make_int4(0, 0, 0, 0);
        if (i4 < N_NODES)   // N_NODES % 4 == 0, so whole-int4 guard is exact
            v = *reinterpret_cast<const int4*>(&g_deg[i4]);
        int tsum = v.x + v.y + v.z + v.w;

        int x = tsum;
#pragma unroll
        for (int o = 1; o < 32; o <<= 1) {
            int y = __shfl_up_sync(0xFFFFFFFFu, x, o);
            if (lane >= o) x += y;
        }
        if (lane == 31) warp_sums[w] = x;
        __syncthreads();
        if (w == 0) {
            int y = warp_sums[lane];
#pragma unroll
            for (int o = 1; o < 32; o <<= 1) {
                int z = __shfl_up_sync(0xFFFFFFFFu, y, o);
                if (lane >= o) y += z;
            }
            warp_sums[lane] = y;
        }
        __syncthreads();

        int excl = (x - tsum) + (w > 0 ? warp_sums[w - 1] : 0) + s_base;
        if (i4 < N_NODES) {
            int p1 = excl + v.x;
            int p2 = p1 + v.y;
            int p3 = p2 + v.z;
            int p4 = p3 + v.w;
            *reinterpret_cast<int4*>(&g_pos[i4]) = make_int4(excl, p1, p2, p3);
            g_off[i4 + 1] = p1;
            g_off[i4 + 2] = p2;
            g_off[i4 + 3] = p3;
            g_off[i4 + 4] = p4;
        }
        __syncthreads();
        if (tid == 0) s_base += warp_sums[31];
        __syncthreads();
    }
}

// ---------------- kernel 4: scatter edges into CSR-by-dst (x4) -------------
__global__ void scatter_kernel(const int* __restrict__ src,
                               const int* __restrict__ dst) {
    int i = blockIdx.x * blockDim.x + threadIdx.x;
    if (i * 4 < E_EDGES) {
        int4 d4 = *reinterpret_cast<const int4*>(&dst[i * 4]);
        int4 s4 = *reinterpret_cast<const int4*>(&src[i * 4]);
        g_csr_src[atomicAdd(&g_pos[d4.x], 1)] = s4.x;
        g_csr_src[atomicAdd(&g_pos[d4.y], 1)] = s4.y;
        g_csr_src[atomicAdd(&g_pos[d4.z], 1)] = s4.z;
        g_csr_src[atomicAdd(&g_pos[d4.w], 1)] = s4.w;
    }
}

// ---------------- kernel 5: fused softmax + aggregation, 1 warp / dst ------
// Softmax shift dropped: scores are leaky_relu of small dot sums (|x| << 80),
// exp cannot overflow, and softmax is shift-invariant.
__global__ __launch_bounds__(256) void agg_kernel(const float* __restrict__ bias,
                                                  float* __restrict__ out) {
    int d    = (blockIdx.x * blockDim.x + threadIdx.x) >> 5;
    int lane = threadIdx.x & 31;
    if (d >= N_NODES) return;

    int start = g_off[d];
    int end   = g_off[d + 1];

    int   h  = lane >> 3;                 // head owning lanes' 4 output dims
    float er = g_er[d * H_HEADS + h];

    float4 acc  = make_float4(0.f, 0.f, 0.f, 0.f);
    float  ssum = 0.f;

    for (int j = start; j < end; ++j) {
        int   s = g_csr_src[j];           // warp-uniform broadcast
        float x = g_el[s * H_HEADS + h] + er;
        x = (x > 0.f) ? x : NEG_SLOPE * x;
        float a = __expf(x);              // same across the 8 lanes of a head
        ssum += a;
        float4 f = *reinterpret_cast<const float4*>(
            &g_ft[(size_t)s * M_OUT + lane * 4]);
        acc.x += f.x * a; acc.y += f.y * a; acc.z += f.z * a; acc.w += f.w * a;
    }
    float inv = (end > start) ? 1.f / ssum : 0.f;

    float4 b = *reinterpret_cast<const float4*>(&bias[lane * 4]);
    float4 o;
    o.x = acc.x * inv + b.x;
    o.y = acc.y * inv + b.y;
    o.z = acc.z * inv + b.z;
    o.w = acc.w * inv + b.w;
    *reinterpret_cast<float4*>(&out[(size_t)d * M_OUT + lane * 4]) = o;
}

// ---------------- launch ----------------------------------------------------
extern "C" void kernel_launch(void* const* d_in, const int* in_sizes, int n_in,
                              void* d_out, int out_size) {
    const float* feat   = (const float*)d_in[0];
    const int*   src    = (const int*)d_in[1];
    const int*   dst    = (const int*)d_in[2];
    const float* W      = (const float*)d_in[3];
    const float* attn_l = (const float*)d_in[4];
    const float* attn_r = (const float*)d_in[5];
    const float* bias   = (const float*)d_in[6];
    float* out = (float*)d_out;

    zero_kernel<<<(N_NODES / 4 + 255) / 256, 256>>>();
    gemm_kernel<<<(N_NODES + BR - 1) / BR, 256>>>(feat, W, attn_l, attn_r);
    hist_kernel<<<(E_EDGES / 4 + 255) / 256, 256>>>(dst);
    scan_kernel<<<1, 1024>>>();
    scatter_kernel<<<(E_EDGES / 4 + 255) / 256, 256>>>(src, dst);
    agg_kernel<<<(N_NODES + 7) / 8, 256>>>(bias, out);
}

// round 13
// speedup vs baseline: 1.1745x; 1.0699x over previous
#include <cuda_runtime.h>
#include <cuda_bf16.h>
#include <math.h>

// Problem constants (match reference)
#define N_NODES 50000
#define E_EDGES 800000
#define K_IN    256
#define M_OUT   128   // H*D = 4*32
#define H_HEADS 4
#define D_HEAD  32
#define NEG_SLOPE 0.2f

#define SCAN_CHUNK 4096
#define SCAN_BLOCKS ((N_NODES + SCAN_CHUNK - 1) / SCAN_CHUNK)   // 13

typedef unsigned long long ull;

// ---------------- scratch (device globals; no allocation allowed) ----------
__device__ float g_ft[(size_t)N_NODES * M_OUT];   // projected features [N,128]
__device__ float g_el[N_NODES * H_HEADS];         // per-node left logits
__device__ float g_er[N_NODES * H_HEADS];         // per-node right logits
__device__ int   g_deg[N_NODES];
__device__ int   g_pos[N_NODES];                  // running fill cursor (init = offsets)
__device__ int   g_off[N_NODES + 1];
__device__ int   g_csr_src[E_EDGES];
__device__ int   g_bsum[SCAN_BLOCKS];             // per-chunk sums for 2-phase scan

// ---------------- f32x2 packed-FMA helpers (sm_100+) ----------------------
__device__ __forceinline__ ull pack2(float x, float y) {
    ull r;
    asm("mov.b64 %0, {%1,%2};" : "=l"(r) : "f"(x), "f"(y));
    return r;
}
__device__ __forceinline__ void unpack2(ull v, float& x, float& y) {
    asm("mov.b64 {%0,%1}, %2;" : "=f"(x), "=f"(y) : "l"(v));
}
__device__ __forceinline__ void ffma2(ull& d, ull a, ull b) {
    asm("fma.rn.f32x2 %0, %1, %2, %0;" : "+l"(d) : "l"(a), "l"(b));
}

// ---------------- kernel 0: zero degree counters (int4) --------------------
__global__ void zero_kernel() {
    int i = blockIdx.x * blockDim.x + threadIdx.x;   // 12500 int4
    if (i * 4 < N_NODES)
        *reinterpret_cast<int4*>(&g_deg[i * 4]) = make_int4(0, 0, 0, 0);
}

// ---------------- kernel 1: GEMM ft = feat @ W + fused el/er ---------------
// 64 rows x 128 cols per block, 256 threads.
// warp ty owns rows ty*8..ty*8+7; lane tx owns cols tx*4..tx*4+3.
// A tile stored in smem as duplicated (a,a) f32x2 pairs -> broadcast LDS.128.
// B tile read directly as native f32x2 pairs (adjacent cols) -> no packing.
#define BR 64
#define KC 32
#define BS_LD 132

__global__ __launch_bounds__(256) void gemm_kernel(const float* __restrict__ A,
                                                   const float* __restrict__ B,
                                                   const float* __restrict__ attn_l,
                                                   const float* __restrict__ attn_r) {
    __shared__ ull   As2[KC][BR];      // 16 KB, [k][row] duplicated pairs
    __shared__ float Bs[KC][BS_LD];    // ~16.9 KB

    const int tid  = threadIdx.x;
    const int row0 = blockIdx.x * BR;
    const int ty   = tid >> 5;   // 0..7
    const int tx   = tid & 31;   // 0..31

    // attn slices for fused epilogue
    const float4 al = *reinterpret_cast<const float4*>(&attn_l[tx * 4]);
    const float4 ar = *reinterpret_cast<const float4*>(&attn_r[tx * 4]);

    ull acc[8][2];
#pragma unroll
    for (int i = 0; i < 8; i++) { acc[i][0] = 0ULL; acc[i][1] = 0ULL; }

    // A fill: row = tid>>2 (0..63), k offsets (tid&3)*8 .. +7  (8 floats/thread)
    const int a_r = tid >> 2;
    const int a_k = (tid & 3) * 8;
    // B fill: k row = tid>>3 (0..31), col base (tid&7)*16 (16 floats/thread)
    const int b_k = tid >> 3;
    const int b_c = (tid & 7) * 16;

    for (int k0 = 0; k0 < K_IN; k0 += KC) {
        {
            int gr = row0 + a_r;
            float4 v0 = make_float4(0.f, 0.f, 0.f, 0.f), v1 = v0;
            if (gr < N_NODES) {
                const float* ap = &A[(size_t)gr * K_IN + k0 + a_k];
                v0 = *reinterpret_cast<const float4*>(ap);
                v1 = *reinterpret_cast<const float4*>(ap + 4);
            }
            As2[a_k + 0][a_r] = pack2(v0.x, v0.x);
            As2[a_k + 1][a_r] = pack2(v0.y, v0.y);
            As2[a_k + 2][a_r] = pack2(v0.z, v0.z);
            As2[a_k + 3][a_r] = pack2(v0.w, v0.w);
            As2[a_k + 4][a_r] = pack2(v1.x, v1.x);
            As2[a_k + 5][a_r] = pack2(v1.y, v1.y);
            As2[a_k + 6][a_r] = pack2(v1.z, v1.z);
            As2[a_k + 7][a_r] = pack2(v1.w, v1.w);
        }
        {
            const float* bp = &B[(size_t)(k0 + b_k) * M_OUT + b_c];
#pragma unroll
            for (int q = 0; q < 4; q++)
                *reinterpret_cast<float4*>(&Bs[b_k][b_c + q * 4]) =
                    *reinterpret_cast<const float4*>(bp + q * 4);
        }
        __syncthreads();

#pragma unroll
        for (int k = 0; k < KC; k++) {
            // 2 b-pairs (4 cols), no packing needed
            ulonglong2 bb = *reinterpret_cast<const ulonglong2*>(&Bs[k][tx * 4]);
            // 8 a-pairs (8 rows) via 4 broadcast LDS.128
            const ulonglong2* arow =
                reinterpret_cast<const ulonglong2*>(&As2[k][ty * 8]);
            ulonglong2 a01 = arow[0];
            ulonglong2 a23 = arow[1];
            ulonglong2 a45 = arow[2];
            ulonglong2 a67 = arow[3];
            ffma2(acc[0][0], a01.x, bb.x); ffma2(acc[0][1], a01.x, bb.y);
            ffma2(acc[1][0], a01.y, bb.x); ffma2(acc[1][1], a01.y, bb.y);
            ffma2(acc[2][0], a23.x, bb.x); ffma2(acc[2][1], a23.x, bb.y);
            ffma2(acc[3][0], a23.y, bb.x); ffma2(acc[3][1], a23.y, bb.y);
            ffma2(acc[4][0], a45.x, bb.x); ffma2(acc[4][1], a45.x, bb.y);
            ffma2(acc[5][0], a45.y, bb.x); ffma2(acc[5][1], a45.y, bb.y);
            ffma2(acc[6][0], a67.x, bb.x); ffma2(acc[6][1], a67.x, bb.y);
            ffma2(acc[7][0], a67.y, bb.x); ffma2(acc[7][1], a67.y, bb.y);
        }
        __syncthreads();
    }

    // epilogue: store ft rows + fused el/er (dot with attn over 8-lane head groups)
#pragma unroll
    for (int i = 0; i < 8; i++) {
        int gr = row0 + ty * 8 + i;
        if (gr < N_NODES) {
            float4 o;
            unpack2(acc[i][0], o.x, o.y);
            unpack2(acc[i][1], o.z, o.w);
            *reinterpret_cast<float4*>(&g_ft[(size_t)gr * M_OUT + tx * 4]) = o;

            float pl = o.x * al.x + o.y * al.y + o.z * al.z + o.w * al.w;
            float pr = o.x * ar.x + o.y * ar.y + o.z * ar.z + o.w * ar.w;
#pragma unroll
            for (int off = 1; off < 8; off <<= 1) {
                pl += __shfl_xor_sync(0xFFFFFFFFu, pl, off);
                pr += __shfl_xor_sync(0xFFFFFFFFu, pr, off);
            }
            if ((tx & 7) == 0) {
                g_el[gr * H_HEADS + (tx >> 3)] = pl;
                g_er[gr * H_HEADS + (tx >> 3)] = pr;
            }
        }
    }
}

// ---------------- kernel 2: in-degree histogram (4 edges/thread) -----------
__global__ void hist_kernel(const int* __restrict__ dst) {
    int i = blockIdx.x * blockDim.x + threadIdx.x;   // 200000 threads
    if (i * 4 < E_EDGES) {
        int4 d4 = *reinterpret_cast<const int4*>(&dst[i * 4]);
        atomicAdd(&g_deg[d4.x], 1);
        atomicAdd(&g_deg[d4.y], 1);
        atomicAdd(&g_deg[d4.z], 1);
        atomicAdd(&g_deg[d4.w], 1);
    }
}

// ---------------- kernel 3a: per-chunk degree sums (phase 1 of scan) -------
__global__ __launch_bounds__(1024) void scan_reduce_kernel() {
    __shared__ int warp_sums[32];
    const int tid  = threadIdx.x;
    const int lane = tid & 31;
    const int w    = tid >> 5;
    const int i4   = blockIdx.x * SCAN_CHUNK + tid * 4;

    int4 v = make_int4(0, 0, 0, 0);
    if (i4 < N_NODES)   // N_NODES % 4 == 0 -> whole-int4 guard is exact
        v = *reinterpret_cast<const int4*>(&g_deg[i4]);
    int s = v.x + v.y + v.z + v.w;
#pragma unroll
    for (int o = 16; o > 0; o >>= 1) s += __shfl_xor_sync(0xFFFFFFFFu, s, o);
    if (lane == 0) warp_sums[w] = s;
    __syncthreads();
    if (w == 0) {
        int t = warp_sums[lane];
#pragma unroll
        for (int o = 16; o > 0; o >>= 1) t += __shfl_xor_sync(0xFFFFFFFFu, t, o);
        if (lane == 0) g_bsum[blockIdx.x] = t;
    }
}

// ---------------- kernel 3b: per-chunk exclusive scan (phase 2) ------------
__global__ __launch_bounds__(1024) void scan_blocks_kernel() {
    __shared__ int warp_sums[32];
    __shared__ int s_base;
    const int tid  = threadIdx.x;
    const int lane = tid & 31;
    const int w    = tid >> 5;
    const int blk  = blockIdx.x;

    // block base = exclusive prefix of g_bsum over preceding chunks
    if (w == 0) {
        int v = (lane < blk) ? g_bsum[lane] : 0;   // SCAN_BLOCKS=13 <= 32
#pragma unroll
        for (int o = 16; o > 0; o >>= 1) v += __shfl_xor_sync(0xFFFFFFFFu, v, o);
        if (lane == 0) s_base = v;
    }
    if (tid == 0 && blk == 0) g_off[0] = 0;
    __syncthreads();

    const int i4 = blk * SCAN_CHUNK + tid * 4;
    int4 v = make_int4(0, 0, 0, 0);
    if (i4 < N_NODES)
        v = *reinterpret_cast<const int4*>(&g_deg[i4]);
    int tsum = v.x + v.y + v.z + v.w;

    int x = tsum;
#pragma unroll
    for (int o = 1; o < 32; o <<= 1) {
        int y = __shfl_up_sync(0xFFFFFFFFu, x, o);
        if (lane >= o) x += y;
    }
    if (lane == 31) warp_sums[w] = x;
    __syncthreads();
    if (w == 0) {
        int y = warp_sums[lane];
#pragma unroll
        for (int o = 1; o < 32; o <<= 1) {
            int z = __shfl_up_sync(0xFFFFFFFFu, y, o);
            if (lane >= o) y += z;
        }
        warp_sums[lane] = y;
    }
    __syncthreads();

    int excl = (x - tsum) + (w > 0 ? warp_sums[w - 1] : 0) + s_base;
    if (i4 < N_NODES) {
        int p1 = excl + v.x;
        int p2 = p1 + v.y;
        int p3 = p2 + v.z;
        int p4 = p3 + v.w;
        *reinterpret_cast<int4*>(&g_pos[i4]) = make_int4(excl, p1, p2, p3);
        g_off[i4 + 1] = p1;
        g_off[i4 + 2] = p2;
        g_off[i4 + 3] = p3;
        g_off[i4 + 4] = p4;
    }
}

// ---------------- kernel 4: scatter edges into CSR-by-dst (x4) -------------
__global__ void scatter_kernel(const int* __restrict__ src,
                               const int* __restrict__ dst) {
    int i = blockIdx.x * blockDim.x + threadIdx.x;
    if (i * 4 < E_EDGES) {
        int4 d4 = *reinterpret_cast<const int4*>(&dst[i * 4]);
        int4 s4 = *reinterpret_cast<const int4*>(&src[i * 4]);
        g_csr_src[atomicAdd(&g_pos[d4.x], 1)] = s4.x;
        g_csr_src[atomicAdd(&g_pos[d4.y], 1)] = s4.y;
        g_csr_src[atomicAdd(&g_pos[d4.z], 1)] = s4.z;
        g_csr_src[atomicAdd(&g_pos[d4.w], 1)] = s4.w;
    }
}

// ---------------- kernel 5: fused softmax + aggregation, 1 warp / dst ------
// Softmax shift dropped: scores are leaky_relu of small dot sums (|x| << 80),
// exp cannot overflow, and softmax is shift-invariant.
// Software-pipelined: next edge's csr index + el logit prefetched one
// iteration ahead so their L2 latency overlaps the current ft gather.
__global__ __launch_bounds__(256) void agg_kernel(const float* __restrict__ bias,
                                                  float* __restrict__ out) {
    int d    = (blockIdx.x * blockDim.x + threadIdx.x) >> 5;
    int lane = threadIdx.x & 31;
    if (d >= N_NODES) return;

    int start = g_off[d];
    int end   = g_off[d + 1];

    int   h  = lane >> 3;                 // head owning lanes' 4 output dims
    float er = g_er[d * H_HEADS + h];

    float4 acc  = make_float4(0.f, 0.f, 0.f, 0.f);
    float  ssum = 0.f;

    int   s_nx  = 0;
    float el_nx = 0.f;
    if (start < end) {
        s_nx  = g_csr_src[start];
        el_nx = g_el[s_nx * H_HEADS + h];
    }
    for (int j = start; j < end; ++j) {
        int   s   = s_nx;
        float elv = el_nx;
        int   jn  = j + 1;
        if (jn < end) {
            s_nx  = g_csr_src[jn];
            el_nx = g_el[s_nx * H_HEADS + h];
        }
        float4 f = *reinterpret_cast<const float4*>(
            &g_ft[(size_t)s * M_OUT + lane * 4]);
        float x = elv + er;
        x = (x > 0.f) ? x : NEG_SLOPE * x;
        float a = __expf(x);              // same across the 8 lanes of a head
        ssum += a;
        acc.x += f.x * a; acc.y += f.y * a; acc.z += f.z * a; acc.w += f.w * a;
    }
    float inv = (end > start) ? 1.f / ssum : 0.f;

    float4 b = *reinterpret_cast<const float4*>(&bias[lane * 4]);
    float4 o;
    o.x = acc.x * inv + b.x;
    o.y = acc.y * inv + b.y;
    o.z = acc.z * inv + b.z;
    o.w = acc.w * inv + b.w;
    *reinterpret_cast<float4*>(&out[(size_t)d * M_OUT + lane * 4]) = o;
}

// ---------------- launch ----------------------------------------------------
extern "C" void kernel_launch(void* const* d_in, const int* in_sizes, int n_in,
                              void* d_out, int out_size) {
    const float* feat   = (const float*)d_in[0];
    const int*   src    = (const int*)d_in[1];
    const int*   dst    = (const int*)d_in[2];
    const float* W      = (const float*)d_in[3];
    const float* attn_l = (const float*)d_in[4];
    const float* attn_r = (const float*)d_in[5];
    const float* bias   = (const float*)d_in[6];
    float* out = (float*)d_out;

    zero_kernel<<<(N_NODES / 4 + 255) / 256, 256>>>();
    gemm_kernel<<<(N_NODES + BR - 1) / BR, 256>>>(feat, W, attn_l, attn_r);
    hist_kernel<<<(E_EDGES / 4 + 255) / 256, 256>>>(dst);
    scan_reduce_kernel<<<SCAN_BLOCKS, 1024>>>();
    scan_blocks_kernel<<<SCAN_BLOCKS, 1024>>>();
    scatter_kernel<<<(E_EDGES / 4 + 255) / 256, 256>>>(src, dst);
    agg_kernel<<<(N_NODES + 7) / 8, 256>>>(bias, out);
}